// round 10
// baseline (speedup 1.0000x reference)
#include <cuda_runtime.h>
#include <cuda_bf16.h>
#include <math.h>

// ---------------- problem constants ----------------
#define TT   128
#define BB   32
#define NTB  4096            // T*B
#define HID  256
#define FEAT 512
#define FLAT 3136            // 64*7*7
#define NACT 6

// output layout: logits[4096*6], v[4096], h[32*256], c[32*256]
#define OUT_V    24576
#define OUT_H    28672
#define OUT_C    36864

// ---------------- packed f32x2 helpers (LSTM + scalar conv3) ----------------
typedef unsigned long long u64t;
__device__ __forceinline__ u64t pk2(float lo, float hi) {
    u64t r;
    asm("mov.b64 %0, {%1, %2};" : "=l"(r) : "f"(lo), "f"(hi));
    return r;
}
__device__ __forceinline__ void fma2(u64t& d, u64t a, u64t b) {
    asm("fma.rn.f32x2 %0, %1, %2, %0;" : "+l"(d) : "l"(a), "l"(b));
}
__device__ __forceinline__ float2 upk2(u64t v) {
    float2 f;
    asm("mov.b64 {%0, %1}, %2;" : "=f"(f.x), "=f"(f.y) : "l"(v));
    return f;
}

// ---------------- bf16 helpers ----------------
__device__ __forceinline__ void mma_bf16(float c[4], const unsigned a[4],
                                         unsigned b0, unsigned b1) {
    asm volatile(
        "mma.sync.aligned.m16n8k16.row.col.f32.bf16.bf16.f32 "
        "{%0,%1,%2,%3}, {%4,%5,%6,%7}, {%8,%9}, {%0,%1,%2,%3};"
        : "+f"(c[0]), "+f"(c[1]), "+f"(c[2]), "+f"(c[3])
        : "r"(a[0]), "r"(a[1]), "r"(a[2]), "r"(a[3]), "r"(b0), "r"(b1));
}
__device__ __forceinline__ void bf_split(float x, __nv_bfloat16& h, __nv_bfloat16& l) {
    h = __float2bfloat16(x);
    l = __float2bfloat16(x - __bfloat162float(h));
}
__device__ __forceinline__ unsigned pack_bf2(__nv_bfloat16 a, __nv_bfloat16 b) {
    __nv_bfloat162 v(a, b);
    return *(unsigned*)&v;
}
__device__ __forceinline__ unsigned lo32(u64t v) { return (unsigned)v; }
__device__ __forceinline__ unsigned hi32(u64t v) { return (unsigned)(v >> 32); }

// ---------------- scratch ----------------
__device__ float g_c1[(size_t)NTB*32*20*20];
__device__ float g_c2[(size_t)NTB*64*9*9];
__device__ float g_c3[(size_t)NTB*64*7*7];
__device__ float g_feat[(size_t)NTB*FEAT];
__device__ float g_gx[(size_t)NTB*4*HID];
__device__ float g_hs[(size_t)NTB*HID];
__device__ float g_h[BB*HID];
__device__ unsigned g_bar;
__device__ unsigned g_exit;

// ======================================================================
// bf16x3 implicit-GEMM conv, hi/lo INTERLEAVED smem (LDS.64 loads).
// Input word-pair v: iw[2v]=hi-word, iw[2v+1]=lo-word.
// Weight row m, k-pair q: ww[m*WSW+2q]=hi, +1=lo.  WSW = KC+2 (even).
// 3 MMAs per k16: hh + hl + lh  (== round-9 numerics exactly).
// ======================================================================
template<int CIN,int KW,int S,int IW,int OW,int MCH,int KC,int NG,int MAXNT,bool SCALE>
__global__ void __launch_bounds__(256, 2)
conv_bf3_kernel(const float* __restrict__ src,
                const float* __restrict__ w,
                const float* __restrict__ bias,
                float* __restrict__ dst) {
    constexpr int K    = CIN * KW * KW;
    constexpr int NPOS = OW * OW;
    constexpr int ISZ  = CIN * IW * IW;
    constexpr int NCH  = K / KC;
    constexpr int WSW  = KC + 2;        // words per weight row (interleaved)
    constexpr int NTT  = (NPOS + 7) / 8;
    constexpr int IPAIR = ISZ / 2;

    extern __shared__ unsigned smw[];
    unsigned* iw = smw;                         // (IPAIR+8)*2 words
    unsigned* ww = iw + (IPAIR + 8) * 2;        // MCH*WSW words
    int* kof = (int*)(ww + MCH * WSW);          // [K]

    int n = blockIdx.x, t = threadIdx.x;

    // input load + hi/lo split, interleaved pack
    const float* s = src + (size_t)n * ISZ;
    for (int i = t; i < IPAIR; i += 256) {
        float x0 = s[2 * i], x1 = s[2 * i + 1];
        if (SCALE) { x0 *= (1.0f / 255.0f); x1 *= (1.0f / 255.0f); }
        __nv_bfloat16 h0, l0, h1, l1;
        bf_split(x0, h0, l0);
        bf_split(x1, h1, l1);
        iw[2 * i]     = pack_bf2(h0, h1);
        iw[2 * i + 1] = pack_bf2(l0, l1);
    }
    if (t < 16) iw[IPAIR * 2 + t] = 0u;
    for (int i = t; i < K; i += 256) {
        int c = i / (KW * KW), r = i % (KW * KW);
        kof[i] = (c * IW + r / KW) * IW + (r % KW);
    }

    int wid = t >> 5, lane = t & 31;
    int gid = lane >> 2, tid4 = lane & 3;
    int wm, ng;
    if (MCH == 32) { wm = wid >> 2; ng = wid & 3; }
    else           { wm = wid >> 1; ng = wid & 1; }
    int m0 = wm * 16 + gid;

    int nbase[MAXNT];
    bool nval[MAXNT];
#pragma unroll
    for (int j = 0; j < MAXNT; j++) {
        int nt = ng + j * NG;
        int p = nt * 8 + gid;
        bool v = (nt < NTT) && (p < NPOS);
        nval[j] = v;
        int oy = p / OW, ox = p % OW;
        nbase[j] = v ? (oy * S * IW + ox * S) : 0;
    }

    float acc[MAXNT][4];
#pragma unroll
    for (int j = 0; j < MAXNT; j++)
        acc[j][0] = acc[j][1] = acc[j][2] = acc[j][3] = 0.f;

    for (int ck = 0; ck < NCH; ck++) {
        __syncthreads();
        for (int i = t; i < MCH * (KC / 2); i += 256) {
            int m = i / (KC / 2), q = i % (KC / 2);
            float x0 = w[(size_t)m * K + ck * KC + 2 * q];
            float x1 = w[(size_t)m * K + ck * KC + 2 * q + 1];
            __nv_bfloat16 h0, l0, h1, l1;
            bf_split(x0, h0, l0);
            bf_split(x1, h1, l1);
            ww[m * WSW + 2 * q]     = pack_bf2(h0, h1);
            ww[m * WSW + 2 * q + 1] = pack_bf2(l0, l1);
        }
        __syncthreads();

        for (int k16 = 0; k16 < KC / 16; k16++) {
            int wq = k16 * 8 + tid4;          // k-pair index within chunk
            u64t A0 = *(const u64t*)&ww[m0 * WSW + 2 * wq];
            u64t A1 = *(const u64t*)&ww[(m0 + 8) * WSW + 2 * wq];
            u64t A2 = *(const u64t*)&ww[m0 * WSW + 2 * wq + 8];
            u64t A3 = *(const u64t*)&ww[(m0 + 8) * WSW + 2 * wq + 8];
            unsigned ah[4] = {lo32(A0), lo32(A1), lo32(A2), lo32(A3)};
            unsigned al[4] = {hi32(A0), hi32(A1), hi32(A2), hi32(A3)};

            int kbase = ck * KC + k16 * 16;
            int oa = kof[kbase + 2 * tid4];        // even, pair-adjacent
            int ob = kof[kbase + 8 + 2 * tid4];
#pragma unroll
            for (int j = 0; j < MAXNT; j++) {
                unsigned b0h, b1h, b0l, b1l;
                if (nval[j]) {
                    u64t B0 = *(const u64t*)&iw[(oa + nbase[j])];   // word idx = 2*pair
                    u64t B1 = *(const u64t*)&iw[(ob + nbase[j])];
                    b0h = lo32(B0); b0l = hi32(B0);
                    b1h = lo32(B1); b1l = hi32(B1);
                } else {
                    b0h = b1h = b0l = b1l = 0u;
                }
                mma_bf16(acc[j], ah, b0h, b1h);
                mma_bf16(acc[j], ah, b0l, b1l);
                mma_bf16(acc[j], al, b0h, b1h);
            }
        }
    }

    float* base = dst + (size_t)n * MCH * NPOS;
    float b0 = __ldg(&bias[m0]);
    float b1 = __ldg(&bias[m0 + 8]);
#pragma unroll
    for (int j = 0; j < MAXNT; j++) {
        int nt = ng + j * NG;
        if (nt >= NTT) continue;
        int col = nt * 8 + tid4 * 2;
        if (col < NPOS) {
            base[(size_t)m0 * NPOS + col]       = fmaxf(acc[j][0] + b0, 0.f);
            base[(size_t)(m0 + 8) * NPOS + col] = fmaxf(acc[j][2] + b1, 0.f);
        }
        if (col + 1 < NPOS) {
            base[(size_t)m0 * NPOS + col + 1]       = fmaxf(acc[j][1] + b0, 0.f);
            base[(size_t)(m0 + 8) * NPOS + col + 1] = fmaxf(acc[j][3] + b1, 0.f);
        }
    }
}

// conv1: CIN=3 KW=8 S=4 IW=84 OW=20 MCH=32 K=192 KC=96  NG=4 MAXNT=13 SCALE
// conv2: CIN=32 KW=4 S=2 IW=20 OW=9  MCH=64 K=512 KC=128 NG=2 MAXNT=6
#define C1B_SMEM (((21168/2 + 8) * 2 + 32 * 98) * 4 + 192 * 4)
#define C2B_SMEM (((12800/2 + 8) * 2 + 64 * 130) * 4 + 512 * 4)

// ======================================================================
// conv3: (n,64,9,9) -> (n,64,7,7), k=3 s=1, relu.  (proven scalar)
// ======================================================================
#define C3_THREADS 128
#define C3_SMEM ((5184 + 9216) * 4)
__global__ void __launch_bounds__(C3_THREADS, 3)
conv3_kernel(const float* __restrict__ w,
             const float* __restrict__ bias) {
    extern __shared__ float sm[];
    float* in = sm;            // 5184
    float* wc = sm + 5184;     // [cc=16][ky][kx][64]
    int n = blockIdx.x;
    const float* src = g_c2 + (size_t)n * 5184;
    for (int i = threadIdx.x; i < 5184; i += C3_THREADS) in[i] = src[i];

    int t = threadIdx.x;
    bool act = t < 100;
    int cot = t / 25, p = t % 25;
    bool has2 = p < 24;
    int p2 = has2 ? p + 25 : p;
    int oy1 = p / 7, ox1 = p % 7;
    int oy2 = p2 / 7, ox2 = p2 % 7;
    u64t a1[8], a2[8];
    u64t z = pk2(0.f, 0.f);
#pragma unroll
    for (int i = 0; i < 8; i++) { a1[i] = z; a2[i] = z; }

    for (int ck = 0; ck < 4; ck++) {
        __syncthreads();
        for (int i = t; i < 9216; i += C3_THREADS) {
            int co = i & 63; int rest = i >> 6;
            int kx = rest % 3; rest /= 3;
            int ky = rest % 3; int cc = rest / 3;
            wc[i] = w[((co * 64 + ck * 16 + cc) * 3 + ky) * 3 + kx];
        }
        __syncthreads();
        if (act) {
            for (int cc = 0; cc < 16; cc++) {
                int c = ck * 16 + cc;
#pragma unroll
                for (int ky = 0; ky < 3; ky++) {
                    const float* b1 = &in[(c * 9 + oy1 + ky) * 9 + ox1];
                    const float* b2 = &in[(c * 9 + oy2 + ky) * 9 + ox2];
                    float r1[3], r2[3];
#pragma unroll
                    for (int kx = 0; kx < 3; kx++) { r1[kx] = b1[kx]; r2[kx] = b2[kx]; }
#pragma unroll
                    for (int kx = 0; kx < 3; kx++) {
                        const ulonglong2* wq = (const ulonglong2*)&wc[((cc * 3 + ky) * 3 + kx) * 64 + cot * 16];
                        ulonglong2 w0 = wq[0], w1 = wq[1], w2 = wq[2], w3 = wq[3];
                        u64t x1 = pk2(r1[kx], r1[kx]);
                        u64t x2 = pk2(r2[kx], r2[kx]);
                        fma2(a1[0], x1, w0.x); fma2(a1[1], x1, w0.y);
                        fma2(a1[2], x1, w1.x); fma2(a1[3], x1, w1.y);
                        fma2(a1[4], x1, w2.x); fma2(a1[5], x1, w2.y);
                        fma2(a1[6], x1, w3.x); fma2(a1[7], x1, w3.y);
                        fma2(a2[0], x2, w0.x); fma2(a2[1], x2, w0.y);
                        fma2(a2[2], x2, w1.x); fma2(a2[3], x2, w1.y);
                        fma2(a2[4], x2, w2.x); fma2(a2[5], x2, w2.y);
                        fma2(a2[6], x2, w3.x); fma2(a2[7], x2, w3.y);
                    }
                }
            }
        }
    }
    if (act) {
        float* base = g_c3 + (size_t)n * 3136;
#pragma unroll
        for (int q = 0; q < 8; q++) {
            float2 v1 = upk2(a1[q]), v2 = upk2(a2[q]);
            int co = cot * 16 + q * 2;
            float b0 = bias[co], b1v = bias[co + 1];
            base[(co+0) * 49 + p] = fmaxf(v1.x + b0, 0.f);
            base[(co+1) * 49 + p] = fmaxf(v1.y + b1v, 0.f);
            if (has2) {
                base[(co+0) * 49 + p + 25] = fmaxf(v2.x + b0, 0.f);
                base[(co+1) * 49 + p + 25] = fmaxf(v2.y + b1v, 0.f);
            }
        }
    }
}

// ======================================================================
// bf16x3 GEMM, hi/lo INTERLEAVED smem (LDS.64 frags):
// C[M,N] = A[M,K] @ Bw[N,K]^T + b1 (+b2), opt relu.
// 128x128 CTA, BK=16, 256 threads (8 warps: 4Mx2N, warp tile 32x64),
// double-buffered.  Row = 16 words (8 kpairs x {hi,lo}), stride 20 words.
// ======================================================================
#define GEMM_RSW 20
#define GEMM_BUFW (128 * GEMM_RSW)          // words per buffer per operand
#define GEMM_SMEM (2 * 2 * GEMM_BUFW * 4)   // 40960 B
template <bool RELU>
__global__ void __launch_bounds__(256)
gemm_bf3_kernel(const float* __restrict__ A,
                const float* __restrict__ Bw,
                const float* __restrict__ bias1,
                const float* __restrict__ bias2,
                float* __restrict__ C,
                int M, int N, int K) {
    extern __shared__ unsigned gsm[];
    unsigned* Aw = gsm;                      // [2][128][20]
    unsigned* Bs = gsm + 2 * GEMM_BUFW;      // [2][128][20]

    int bm = blockIdx.y * 128, bn = blockIdx.x * 128;
    int t = threadIdx.x;
    int wid = t >> 5, lane = t & 31;
    int gid = lane >> 2, tid4 = lane & 3;
    int wm = (wid >> 1) * 32;
    int wn = (wid & 1) * 64;
    int lr = t >> 1, lc = (t & 1) * 8;       // each thread fills 8 floats of one row

    float c[2][8][4];
#pragma unroll
    for (int mt = 0; mt < 2; mt++)
#pragma unroll
        for (int nt = 0; nt < 8; nt++)
#pragma unroll
            for (int q = 0; q < 4; q++) c[mt][nt][q] = 0.f;

    const float* Ap = A + (size_t)(bm + lr) * K + lc;
    const float* Bp = Bw + (size_t)(bn + lr) * K + lc;

    // convert 8 floats -> 8 interleaved words {h,l,h,l,...}, two uint4 stores
    auto fill = [&](unsigned* dst, float4 f0, float4 f1) {
        float v[8] = {f0.x, f0.y, f0.z, f0.w, f1.x, f1.y, f1.z, f1.w};
        unsigned wv[8];
#pragma unroll
        for (int i = 0; i < 4; i++) {
            __nv_bfloat16 h0, l0, h1, l1;
            bf_split(v[2*i], h0, l0);
            bf_split(v[2*i+1], h1, l1);
            wv[2*i]   = pack_bf2(h0, h1);
            wv[2*i+1] = pack_bf2(l0, l1);
        }
        *(uint4*)dst       = make_uint4(wv[0], wv[1], wv[2], wv[3]);
        *(uint4*)(dst + 4) = make_uint4(wv[4], wv[5], wv[6], wv[7]);
    };

    // preload tile 0
    {
        float4 a0 = *(const float4*)(Ap);
        float4 a1 = *(const float4*)(Ap + 4);
        float4 b0 = *(const float4*)(Bp);
        float4 b1 = *(const float4*)(Bp + 4);
        fill(Aw + lr * GEMM_RSW + lc, a0, a1);
        fill(Bs + lr * GEMM_RSW + lc, b0, b1);
    }
    __syncthreads();

    int cur = 0;
    for (int k0 = 0; k0 < K; k0 += 16) {
        bool more = (k0 + 16) < K;
        float4 ga0, ga1, gb0, gb1;
        if (more) {
            ga0 = *(const float4*)(Ap + k0 + 16);
            ga1 = *(const float4*)(Ap + k0 + 20);
            gb0 = *(const float4*)(Bp + k0 + 16);
            gb1 = *(const float4*)(Bp + k0 + 20);
        }
        const unsigned* aw = Aw + cur * GEMM_BUFW;
        const unsigned* bw = Bs + cur * GEMM_BUFW;
        unsigned afh[2][4], afl[2][4];
#pragma unroll
        for (int mt = 0; mt < 2; mt++) {
            int m = wm + mt * 16 + gid;
            u64t A0 = *(const u64t*)&aw[m * GEMM_RSW + 2 * tid4];
            u64t A1 = *(const u64t*)&aw[(m + 8) * GEMM_RSW + 2 * tid4];
            u64t A2 = *(const u64t*)&aw[m * GEMM_RSW + 2 * tid4 + 8];
            u64t A3 = *(const u64t*)&aw[(m + 8) * GEMM_RSW + 2 * tid4 + 8];
            afh[mt][0] = lo32(A0); afh[mt][1] = lo32(A1);
            afh[mt][2] = lo32(A2); afh[mt][3] = lo32(A3);
            afl[mt][0] = hi32(A0); afl[mt][1] = hi32(A1);
            afl[mt][2] = hi32(A2); afl[mt][3] = hi32(A3);
        }
        unsigned bfh[8][2], bfl[8][2];
#pragma unroll
        for (int nt = 0; nt < 8; nt++) {
            int nn = wn + nt * 8 + gid;
            u64t B0 = *(const u64t*)&bw[nn * GEMM_RSW + 2 * tid4];
            u64t B1 = *(const u64t*)&bw[nn * GEMM_RSW + 2 * tid4 + 8];
            bfh[nt][0] = lo32(B0); bfh[nt][1] = lo32(B1);
            bfl[nt][0] = hi32(B0); bfl[nt][1] = hi32(B1);
        }
#pragma unroll
        for (int mt = 0; mt < 2; mt++)
#pragma unroll
            for (int nt = 0; nt < 8; nt++) {
                mma_bf16(c[mt][nt], afh[mt], bfh[nt][0], bfh[nt][1]);
                mma_bf16(c[mt][nt], afh[mt], bfl[nt][0], bfl[nt][1]);
                mma_bf16(c[mt][nt], afl[mt], bfh[nt][0], bfh[nt][1]);
            }
        if (more) {
            int nxt = cur ^ 1;
            fill(Aw + nxt * GEMM_BUFW + lr * GEMM_RSW + lc, ga0, ga1);
            fill(Bs + nxt * GEMM_BUFW + lr * GEMM_RSW + lc, gb0, gb1);
            __syncthreads();
            cur = nxt;
        }
    }

    // epilogue
#pragma unroll
    for (int mt = 0; mt < 2; mt++) {
        int row = bm + wm + mt * 16 + gid;
#pragma unroll
        for (int nt = 0; nt < 8; nt++) {
            int col = bn + wn + nt * 8 + tid4 * 2;
            float bv0 = bias1[col], bv1 = bias1[col + 1];
            if (bias2) { bv0 += bias2[col]; bv1 += bias2[col + 1]; }
            float r0 = c[mt][nt][0] + bv0;
            float r1 = c[mt][nt][1] + bv1;
            float r2 = c[mt][nt][2] + bv0;
            float r3 = c[mt][nt][3] + bv1;
            if (RELU) {
                r0 = fmaxf(r0, 0.f); r1 = fmaxf(r1, 0.f);
                r2 = fmaxf(r2, 0.f); r3 = fmaxf(r3, 0.f);
            }
            *(float2*)&C[(size_t)row * N + col]       = make_float2(r0, r1);
            *(float2*)&C[(size_t)(row + 8) * N + col] = make_float2(r2, r3);
        }
    }
}

// ======================================================================
// persistent LSTM: 128 CTAs, each owns 2 hidden units.  (proven)
// ======================================================================
#define NBLK 128
#define LSTM_SMEM ((2048 + 8224 + 64 + 576) * 4)
__device__ __forceinline__ float sigmoidf(float x) { return 1.f / (1.f + expf(-x)); }

__global__ void __launch_bounds__(256)
lstm_kernel(const float* __restrict__ done,
            const float* __restrict__ h0,
            const float* __restrict__ c0,
            const float* __restrict__ whh,
            float* __restrict__ out) {
    extern __shared__ float sm[];
    float* w_s = sm;             // [k=256][r=8]
    float* h_s = sm + 2048;      // [32][257]
    float* c_s = h_s + 8224;     // [64]
    float* p_s = c_s + 64;       // [2][32][9]
    int t = threadIdx.x, blk = blockIdx.x;
    int j0 = blk * 2;

    for (int i = t; i < 2048; i += 256) {
        int k = i >> 3, r = i & 7;
        int q = r >> 1, jj = r & 1;
        w_s[i] = whh[(size_t)(q * HID + j0 + jj) * HID + k];
    }
    if (t < 64) {
        int b = t >> 1, jj = t & 1;
        c_s[t] = c0[b * HID + j0 + jj];
    }
    __syncthreads();

    int u = t & 127, half = t >> 7;
    int gb = u & 31, rq = u >> 5;
    unsigned target = 0;

    for (int step = 0; step < TT; step++) {
        float2 acc0;
        if (half == 0)
            acc0 = *(const float2*)&g_gx[(size_t)(step * BB + gb) * 4 * HID + rq * HID + j0];
        else
            acc0 = make_float2(0.f, 0.f);
        u64t accp = pk2(acc0.x, acc0.y);

        const float* hsrc = (step == 0) ? h0 : g_h;
        for (int i = t; i < BB * HID; i += 256) {
            int b = i >> 8;
            h_s[b * 257 + (i & 255)] = hsrc[i] * (1.0f - __ldg(&done[step * BB + b]));
        }
        __syncthreads();

        {
            const float* hp = &h_s[gb * 257 + half * 128];
            const float* wp = &w_s[(half * 128) * 8 + rq * 2];
#pragma unroll 8
            for (int k = 0; k < 128; k++) {
                float hv = hp[k];
                u64t hh = pk2(hv, hv);
                u64t wv = *(const u64t*)&wp[k * 8];
                fma2(accp, hh, wv);
            }
            float2 r = upk2(accp);
            float* pp = &p_s[half * 288 + gb * 9 + rq * 2];
            pp[0] = r.x; pp[1] = r.y;
        }
        __syncthreads();

        if (t < 64) {
            int b = t >> 1, jj = t & 1;
            float m = 1.0f - __ldg(&done[step * BB + b]);
            const float* p0 = &p_s[b * 9];
            const float* p1 = &p_s[288 + b * 9];
            float gi = p0[0 + jj] + p1[0 + jj];
            float gf = p0[2 + jj] + p1[2 + jj];
            float gg = p0[4 + jj] + p1[4 + jj];
            float go = p0[6 + jj] + p1[6 + jj];
            float I = sigmoidf(gi);
            float F = sigmoidf(gf);
            float G = tanhf(gg);
            float O = sigmoidf(go);
            float c_new = F * (m * c_s[t]) + I * G;
            c_s[t] = c_new;
            float h_new = O * tanhf(c_new);
            g_h[b * HID + j0 + jj] = h_new;
            g_hs[(size_t)(step * BB + b) * HID + j0 + jj] = h_new;
            if (step == TT - 1) {
                out[OUT_H + b * HID + j0 + jj] = h_new;
                out[OUT_C + b * HID + j0 + jj] = c_new;
            }
        }
        __threadfence();
        __syncthreads();
        if (t == 0) {
            atomicAdd(&g_bar, 1u);
            target += NBLK;
            while (*(volatile unsigned*)&g_bar < target) { }
        }
        __syncthreads();
    }

    if (t == 0) {
        unsigned v = atomicAdd(&g_exit, 1u);
        if (v == NBLK - 1) {
            atomicExch(&g_exit, 0u);
            atomicExch(&g_bar, 0u);
            __threadfence();
        }
    }
}

// ======================================================================
// heads
// ======================================================================
__global__ void heads_kernel(const float* __restrict__ pw,
                             const float* __restrict__ pb,
                             const float* __restrict__ vw,
                             const float* __restrict__ vb,
                             float* __restrict__ out) {
    __shared__ float ws[7 * 256];
    int t = threadIdx.x;
    for (int i = t; i < 6 * 256; i += 256) ws[i] = pw[i];
    if (t < 256) ws[1536 + t] = vw[t];
    __syncthreads();

    int warp = t >> 5, lane = t & 31;
    int row = blockIdx.x * 8 + warp;
    const float* hrow = g_hs + (size_t)row * 256;
    float p[7];
#pragma unroll
    for (int a = 0; a < 7; a++) p[a] = 0.f;
    for (int k = lane; k < 256; k += 32) {
        float hv = hrow[k];
#pragma unroll
        for (int a = 0; a < 7; a++) p[a] += hv * ws[a * 256 + k];
    }
#pragma unroll
    for (int a = 0; a < 7; a++)
#pragma unroll
        for (int off = 16; off; off >>= 1)
            p[a] += __shfl_xor_sync(0xffffffffu, p[a], off);
    if (lane == 0) {
#pragma unroll
        for (int a = 0; a < 6; a++) out[(size_t)row * 6 + a] = p[a] + pb[a];
        out[OUT_V + row] = p[6] + vb[0];
    }
}

// ======================================================================
// launch
// ======================================================================
extern "C" void kernel_launch(void* const* d_in, const int* in_sizes, int n_in,
                              void* d_out, int out_size) {
    const float* image = (const float*)d_in[0];
    const float* done  = (const float*)d_in[1];
    const float* h0    = (const float*)d_in[2];
    const float* c0    = (const float*)d_in[3];
    const float* c1w   = (const float*)d_in[4];
    const float* c1b   = (const float*)d_in[5];
    const float* c2w   = (const float*)d_in[6];
    const float* c2b   = (const float*)d_in[7];
    const float* c3w   = (const float*)d_in[8];
    const float* c3b   = (const float*)d_in[9];
    const float* fcw   = (const float*)d_in[10];
    const float* fcb   = (const float*)d_in[11];
    const float* wih   = (const float*)d_in[12];
    const float* whh   = (const float*)d_in[13];
    const float* bih   = (const float*)d_in[14];
    const float* bhh   = (const float*)d_in[15];
    const float* polw  = (const float*)d_in[16];
    const float* polb  = (const float*)d_in[17];
    const float* valw  = (const float*)d_in[18];
    const float* valb  = (const float*)d_in[19];
    float* out = (float*)d_out;

    auto conv1 = conv_bf3_kernel<3, 8, 4, 84, 20, 32,  96, 4, 13, true>;
    auto conv2 = conv_bf3_kernel<32, 4, 2, 20, 9,  64, 128, 2, 6,  false>;

    cudaFuncSetAttribute(conv1, cudaFuncAttributeMaxDynamicSharedMemorySize, C1B_SMEM);
    cudaFuncSetAttribute(conv2, cudaFuncAttributeMaxDynamicSharedMemorySize, C2B_SMEM);
    cudaFuncSetAttribute(conv3_kernel, cudaFuncAttributeMaxDynamicSharedMemorySize, C3_SMEM);
    cudaFuncSetAttribute(gemm_bf3_kernel<true>,  cudaFuncAttributeMaxDynamicSharedMemorySize, GEMM_SMEM);
    cudaFuncSetAttribute(gemm_bf3_kernel<false>, cudaFuncAttributeMaxDynamicSharedMemorySize, GEMM_SMEM);
    cudaFuncSetAttribute(lstm_kernel, cudaFuncAttributeMaxDynamicSharedMemorySize, LSTM_SMEM);

    void *p_c1, *p_c2, *p_c3, *p_feat, *p_gx;
    cudaGetSymbolAddress(&p_c1, g_c1);
    cudaGetSymbolAddress(&p_c2, g_c2);
    cudaGetSymbolAddress(&p_c3, g_c3);
    cudaGetSymbolAddress(&p_feat, g_feat);
    cudaGetSymbolAddress(&p_gx, g_gx);

    conv1<<<NTB, 256, C1B_SMEM>>>(image, c1w, c1b, (float*)p_c1);
    conv2<<<NTB, 256, C2B_SMEM>>>((const float*)p_c1, c2w, c2b, (float*)p_c2);
    conv3_kernel<<<NTB, C3_THREADS, C3_SMEM>>>(c3w, c3b);

    // feats = relu(flat @ fc_w^T + fc_b)   [4096,512]  (bf16x3 ~= fp32)
    gemm_bf3_kernel<true><<<dim3(FEAT / 128, NTB / 128), 256, GEMM_SMEM>>>(
        (const float*)p_c3, fcw, fcb, nullptr, (float*)p_feat, NTB, FEAT, FLAT);

    // gates_x = feats @ w_ih^T + b_ih + b_hh   [4096,1024]  (bf16x3 ~= fp32)
    gemm_bf3_kernel<false><<<dim3((4 * HID) / 128, NTB / 128), 256, GEMM_SMEM>>>(
        (const float*)p_feat, wih, bih, bhh, (float*)p_gx, NTB, 4 * HID, FEAT);

    lstm_kernel<<<NBLK, 256, LSTM_SMEM>>>(done, h0, c0, whh, out);

    heads_kernel<<<NTB / 8, 256>>>(polw, polb, valw, valb, out);
}

// round 11
// speedup vs baseline: 1.1979x; 1.1979x over previous
#include <cuda_runtime.h>
#include <cuda_bf16.h>
#include <math.h>

// ---------------- problem constants ----------------
#define TT   128
#define BB   32
#define NTB  4096            // T*B
#define HID  256
#define FEAT 512
#define FLAT 3136            // 64*7*7
#define NACT 6

// output layout: logits[4096*6], v[4096], h[32*256], c[32*256]
#define OUT_V    24576
#define OUT_H    28672
#define OUT_C    36864

// ---------------- packed f32x2 helpers (LSTM) ----------------
typedef unsigned long long u64t;
__device__ __forceinline__ u64t pk2(float lo, float hi) {
    u64t r;
    asm("mov.b64 %0, {%1, %2};" : "=l"(r) : "f"(lo), "f"(hi));
    return r;
}
__device__ __forceinline__ void fma2(u64t& d, u64t a, u64t b) {
    asm("fma.rn.f32x2 %0, %1, %2, %0;" : "+l"(d) : "l"(a), "l"(b));
}
__device__ __forceinline__ float2 upk2(u64t v) {
    float2 f;
    asm("mov.b64 {%0, %1}, %2;" : "=f"(f.x), "=f"(f.y) : "l"(v));
    return f;
}

// ---------------- bf16 helpers ----------------
__device__ __forceinline__ void mma_bf16(float c[4], const unsigned a[4],
                                         unsigned b0, unsigned b1) {
    asm volatile(
        "mma.sync.aligned.m16n8k16.row.col.f32.bf16.bf16.f32 "
        "{%0,%1,%2,%3}, {%4,%5,%6,%7}, {%8,%9}, {%0,%1,%2,%3};"
        : "+f"(c[0]), "+f"(c[1]), "+f"(c[2]), "+f"(c[3])
        : "r"(a[0]), "r"(a[1]), "r"(a[2]), "r"(a[3]), "r"(b0), "r"(b1));
}
__device__ __forceinline__ void bf_split(float x, __nv_bfloat16& h, __nv_bfloat16& l) {
    h = __float2bfloat16(x);
    l = __float2bfloat16(x - __bfloat162float(h));
}
__device__ __forceinline__ unsigned pack_bf2(__nv_bfloat16 a, __nv_bfloat16 b) {
    __nv_bfloat162 v(a, b);
    return *(unsigned*)&v;
}
__device__ __forceinline__ unsigned lo32(u64t v) { return (unsigned)v; }
__device__ __forceinline__ unsigned hi32(u64t v) { return (unsigned)(v >> 32); }

// ---------------- scratch ----------------
__device__ float g_c1[(size_t)NTB*32*20*20];
__device__ float g_c2[(size_t)NTB*64*9*9];
__device__ float g_c3[(size_t)NTB*64*7*7];
__device__ float g_feat[(size_t)NTB*FEAT];
__device__ float g_gx[(size_t)NTB*4*HID];
__device__ float g_hs[(size_t)NTB*HID];
__device__ float g_h[BB*HID];
__device__ unsigned g_bar;
__device__ unsigned g_exit;

// ======================================================================
// bf16x3 implicit-GEMM conv, hi/lo INTERLEAVED smem (round-10 convs,
// kept: they were the improving part of round 10).
// ======================================================================
template<int CIN,int KW,int S,int IW,int OW,int MCH,int KC,int NG,int MAXNT,bool SCALE>
__global__ void __launch_bounds__(256, 2)
conv_bf3_kernel(const float* __restrict__ src,
                const float* __restrict__ w,
                const float* __restrict__ bias,
                float* __restrict__ dst) {
    constexpr int K    = CIN * KW * KW;
    constexpr int NPOS = OW * OW;
    constexpr int ISZ  = CIN * IW * IW;
    constexpr int NCH  = K / KC;
    constexpr int WSW  = KC + 2;
    constexpr int NTT  = (NPOS + 7) / 8;
    constexpr int IPAIR = ISZ / 2;

    extern __shared__ unsigned smw[];
    unsigned* iw = smw;                         // (IPAIR+8)*2 words
    unsigned* ww = iw + (IPAIR + 8) * 2;        // MCH*WSW words
    int* kof = (int*)(ww + MCH * WSW);          // [K]

    int n = blockIdx.x, t = threadIdx.x;

    const float* s = src + (size_t)n * ISZ;
    for (int i = t; i < IPAIR; i += 256) {
        float x0 = s[2 * i], x1 = s[2 * i + 1];
        if (SCALE) { x0 *= (1.0f / 255.0f); x1 *= (1.0f / 255.0f); }
        __nv_bfloat16 h0, l0, h1, l1;
        bf_split(x0, h0, l0);
        bf_split(x1, h1, l1);
        iw[2 * i]     = pack_bf2(h0, h1);
        iw[2 * i + 1] = pack_bf2(l0, l1);
    }
    if (t < 16) iw[IPAIR * 2 + t] = 0u;
    for (int i = t; i < K; i += 256) {
        int c = i / (KW * KW), r = i % (KW * KW);
        kof[i] = (c * IW + r / KW) * IW + (r % KW);
    }

    int wid = t >> 5, lane = t & 31;
    int gid = lane >> 2, tid4 = lane & 3;
    int wm, ng;
    if (MCH == 32) { wm = wid >> 2; ng = wid & 3; }
    else           { wm = wid >> 1; ng = wid & 1; }
    int m0 = wm * 16 + gid;

    int nbase[MAXNT];
    bool nval[MAXNT];
#pragma unroll
    for (int j = 0; j < MAXNT; j++) {
        int nt = ng + j * NG;
        int p = nt * 8 + gid;
        bool v = (nt < NTT) && (p < NPOS);
        nval[j] = v;
        int oy = p / OW, ox = p % OW;
        nbase[j] = v ? (oy * S * IW + ox * S) : 0;
    }

    float acc[MAXNT][4];
#pragma unroll
    for (int j = 0; j < MAXNT; j++)
        acc[j][0] = acc[j][1] = acc[j][2] = acc[j][3] = 0.f;

    for (int ck = 0; ck < NCH; ck++) {
        __syncthreads();
        for (int i = t; i < MCH * (KC / 2); i += 256) {
            int m = i / (KC / 2), q = i % (KC / 2);
            float x0 = w[(size_t)m * K + ck * KC + 2 * q];
            float x1 = w[(size_t)m * K + ck * KC + 2 * q + 1];
            __nv_bfloat16 h0, l0, h1, l1;
            bf_split(x0, h0, l0);
            bf_split(x1, h1, l1);
            ww[m * WSW + 2 * q]     = pack_bf2(h0, h1);
            ww[m * WSW + 2 * q + 1] = pack_bf2(l0, l1);
        }
        __syncthreads();

        for (int k16 = 0; k16 < KC / 16; k16++) {
            int wq = k16 * 8 + tid4;
            u64t A0 = *(const u64t*)&ww[m0 * WSW + 2 * wq];
            u64t A1 = *(const u64t*)&ww[(m0 + 8) * WSW + 2 * wq];
            u64t A2 = *(const u64t*)&ww[m0 * WSW + 2 * wq + 8];
            u64t A3 = *(const u64t*)&ww[(m0 + 8) * WSW + 2 * wq + 8];
            unsigned ah[4] = {lo32(A0), lo32(A1), lo32(A2), lo32(A3)};
            unsigned al[4] = {hi32(A0), hi32(A1), hi32(A2), hi32(A3)};

            int kbase = ck * KC + k16 * 16;
            int oa = kof[kbase + 2 * tid4];
            int ob = kof[kbase + 8 + 2 * tid4];
#pragma unroll
            for (int j = 0; j < MAXNT; j++) {
                unsigned b0h, b1h, b0l, b1l;
                if (nval[j]) {
                    u64t B0 = *(const u64t*)&iw[(oa + nbase[j])];
                    u64t B1 = *(const u64t*)&iw[(ob + nbase[j])];
                    b0h = lo32(B0); b0l = hi32(B0);
                    b1h = lo32(B1); b1l = hi32(B1);
                } else {
                    b0h = b1h = b0l = b1l = 0u;
                }
                mma_bf16(acc[j], ah, b0h, b1h);
                mma_bf16(acc[j], ah, b0l, b1l);
                mma_bf16(acc[j], al, b0h, b1h);
            }
        }
    }

    float* base = dst + (size_t)n * MCH * NPOS;
    float b0 = __ldg(&bias[m0]);
    float b1 = __ldg(&bias[m0 + 8]);
#pragma unroll
    for (int j = 0; j < MAXNT; j++) {
        int nt = ng + j * NG;
        if (nt >= NTT) continue;
        int col = nt * 8 + tid4 * 2;
        if (col < NPOS) {
            base[(size_t)m0 * NPOS + col]       = fmaxf(acc[j][0] + b0, 0.f);
            base[(size_t)(m0 + 8) * NPOS + col] = fmaxf(acc[j][2] + b1, 0.f);
        }
        if (col + 1 < NPOS) {
            base[(size_t)m0 * NPOS + col + 1]       = fmaxf(acc[j][1] + b0, 0.f);
            base[(size_t)(m0 + 8) * NPOS + col + 1] = fmaxf(acc[j][3] + b1, 0.f);
        }
    }
}

#define C1B_SMEM (((21168/2 + 8) * 2 + 32 * 98) * 4 + 192 * 4)
#define C2B_SMEM (((12800/2 + 8) * 2 + 64 * 130) * 4 + 512 * 4)

// ======================================================================
// conv3 bf16x3 MMA: (n,64,9,9) -> (n,64,7,7), k=3 s=1, relu.
// KW padded 3->4 (zero weights at kx=3) so k-pairs are input-adjacent.
// Dual input planes: iw (normal) + jw (shifted by 1 element) so ODD gather
// addresses also hit one aligned LDS.64.  K=768, KC=192, 4 chunks.
// ======================================================================
#define C3M_ISZ   5184
#define C3M_IPAIR 2592
#define C3M_IWRDS ((C3M_IPAIR + 8) * 2)   // 5200 words per plane
#define C3M_WSW   194                      // 192 + 2 pad
#define C3M_SMEM  ((2 * C3M_IWRDS + 64 * C3M_WSW) * 4 + 768 * 4)
__global__ void __launch_bounds__(256, 2)
conv3_mma_kernel(const float* __restrict__ src,
                 const float* __restrict__ w,
                 const float* __restrict__ bias,
                 float* __restrict__ dst) {
    constexpr int IW = 9, OW = 7, NPOS = 49, MCH = 64;
    constexpr int K = 768, KC = 192, NCH = 4;
    constexpr int NTT = 7, NG = 2, MAXNT = 4;

    extern __shared__ unsigned smw[];
    unsigned* iw = smw;                       // 5200 words
    unsigned* jw = iw + C3M_IWRDS;            // 5200 words (shifted plane)
    unsigned* ww = jw + C3M_IWRDS;            // 64*194
    int* kof = (int*)(ww + 64 * C3M_WSW);     // [768]

    int n = blockIdx.x, t = threadIdx.x;
    const float* s = src + (size_t)n * C3M_ISZ;

    // both planes: iw pair u = elems (2u,2u+1); jw pair u = elems (2u+1,2u+2)
    for (int u = t; u < C3M_IPAIR + 8; u += 256) {
        float x0 = (2*u   < C3M_ISZ) ? s[2*u]   : 0.f;
        float x1 = (2*u+1 < C3M_ISZ) ? s[2*u+1] : 0.f;
        float x2 = (2*u+2 < C3M_ISZ) ? s[2*u+2] : 0.f;
        __nv_bfloat16 h0,l0,h1,l1,h2,l2;
        bf_split(x0,h0,l0); bf_split(x1,h1,l1); bf_split(x2,h2,l2);
        iw[2*u]   = pack_bf2(h0,h1); iw[2*u+1] = pack_bf2(l0,l1);
        jw[2*u]   = pack_bf2(h1,h2); jw[2*u+1] = pack_bf2(l1,l2);
    }
    // kof: k = (c*3+ky)*4+kx, kx in 0..3 (kx=3 is the zero-weight pad)
    for (int i = t; i < K; i += 256) {
        int kx = i & 3, ky = (i >> 2) % 3, c = i / 12;
        kof[i] = c * 81 + ky * 9 + kx;
    }

    int wid = t >> 5, lane = t & 31;
    int gid = lane >> 2, tid4 = lane & 3;
    int wm = wid >> 1, ng = wid & 1;       // 4 m-tiles x 2 n-groups
    int m0 = wm * 16 + gid;

    int nbase[MAXNT];
    bool nval[MAXNT];
#pragma unroll
    for (int j = 0; j < MAXNT; j++) {
        int nt = ng + j * NG;
        int p = nt * 8 + gid;
        bool v = (nt < NTT) && (p < NPOS);
        nval[j] = v;
        int oy = p / OW, ox = p % OW;
        nbase[j] = v ? (oy * IW + ox) : 0;
    }

    float acc[MAXNT][4];
#pragma unroll
    for (int j = 0; j < MAXNT; j++)
        acc[j][0] = acc[j][1] = acc[j][2] = acc[j][3] = 0.f;

    for (int ck = 0; ck < NCH; ck++) {
        __syncthreads();
        // weights: even k -> kx in {0,2}; k+1 -> kx in {1,3}; kx==3 is zero
        for (int i = t; i < MCH * (KC / 2); i += 256) {
            int m = i / (KC / 2), q = i % (KC / 2);
            int k = ck * KC + 2 * q;
            int kx = k & 3, ky = (k >> 2) % 3, c = k / 12;
            float x0 = w[((size_t)(m * 64 + c) * 3 + ky) * 3 + kx];
            float x1 = (kx == 0) ? w[((size_t)(m * 64 + c) * 3 + ky) * 3 + 1] : 0.f;
            __nv_bfloat16 h0, l0, h1, l1;
            bf_split(x0, h0, l0);
            bf_split(x1, h1, l1);
            ww[m * C3M_WSW + 2 * q]     = pack_bf2(h0, h1);
            ww[m * C3M_WSW + 2 * q + 1] = pack_bf2(l0, l1);
        }
        __syncthreads();

        for (int k16 = 0; k16 < KC / 16; k16++) {
            int wq = k16 * 8 + tid4;
            u64t A0 = *(const u64t*)&ww[m0 * C3M_WSW + 2 * wq];
            u64t A1 = *(const u64t*)&ww[(m0 + 8) * C3M_WSW + 2 * wq];
            u64t A2 = *(const u64t*)&ww[m0 * C3M_WSW + 2 * wq + 8];
            u64t A3 = *(const u64t*)&ww[(m0 + 8) * C3M_WSW + 2 * wq + 8];
            unsigned ah[4] = {lo32(A0), lo32(A1), lo32(A2), lo32(A3)};
            unsigned al[4] = {hi32(A0), hi32(A1), hi32(A2), hi32(A3)};

            int kbase = ck * KC + k16 * 16;
            int oa = kof[kbase + 2 * tid4];
            int ob = kof[kbase + 8 + 2 * tid4];
#pragma unroll
            for (int j = 0; j < MAXNT; j++) {
                unsigned b0h, b1h, b0l, b1l;
                if (nval[j]) {
                    int e0 = oa + nbase[j];
                    int e1 = ob + nbase[j];
                    const unsigned* p0 = (e0 & 1) ? (jw + e0 - 1) : (iw + e0);
                    const unsigned* p1 = (e1 & 1) ? (jw + e1 - 1) : (iw + e1);
                    u64t B0 = *(const u64t*)p0;
                    u64t B1 = *(const u64t*)p1;
                    b0h = lo32(B0); b0l = hi32(B0);
                    b1h = lo32(B1); b1l = hi32(B1);
                } else {
                    b0h = b1h = b0l = b1l = 0u;
                }
                mma_bf16(acc[j], ah, b0h, b1h);
                mma_bf16(acc[j], ah, b0l, b1l);
                mma_bf16(acc[j], al, b0h, b1h);
            }
        }
    }

    float* base = dst + (size_t)n * MCH * NPOS;
    float b0 = __ldg(&bias[m0]);
    float b1 = __ldg(&bias[m0 + 8]);
#pragma unroll
    for (int j = 0; j < MAXNT; j++) {
        int nt = ng + j * NG;
        if (nt >= NTT) continue;
        int col = nt * 8 + tid4 * 2;
        if (col < NPOS) {
            base[(size_t)m0 * NPOS + col]       = fmaxf(acc[j][0] + b0, 0.f);
            base[(size_t)(m0 + 8) * NPOS + col] = fmaxf(acc[j][2] + b1, 0.f);
        }
        if (col + 1 < NPOS) {
            base[(size_t)m0 * NPOS + col + 1]       = fmaxf(acc[j][1] + b0, 0.f);
            base[(size_t)(m0 + 8) * NPOS + col + 1] = fmaxf(acc[j][3] + b1, 0.f);
        }
    }
}

// ======================================================================
// bf16x3 GEMM (round-9 proven, 187us): separate hi/lo planes.
// ======================================================================
#define GEMM_SMEM 49152
template <bool RELU>
__global__ void __launch_bounds__(256)
gemm_bf3_kernel(const float* __restrict__ A,
                const float* __restrict__ Bw,
                const float* __restrict__ bias1,
                const float* __restrict__ bias2,
                float* __restrict__ C,
                int M, int N, int K) {
    extern __shared__ __nv_bfloat16 gsm[];
    __nv_bfloat16* Ah = gsm;            // [2][128][24]
    __nv_bfloat16* Al = gsm + 6144;
    __nv_bfloat16* Bh = gsm + 12288;
    __nv_bfloat16* Bl = gsm + 18432;

    int bm = blockIdx.y * 128, bn = blockIdx.x * 128;
    int t = threadIdx.x;
    int wid = t >> 5, lane = t & 31;
    int gid = lane >> 2, tid4 = lane & 3;
    int wm = (wid >> 1) * 32;
    int wn = (wid & 1) * 64;
    int lr = t >> 1, lc = (t & 1) * 8;

    float c[2][8][4];
#pragma unroll
    for (int mt = 0; mt < 2; mt++)
#pragma unroll
        for (int nt = 0; nt < 8; nt++)
#pragma unroll
            for (int q = 0; q < 4; q++) c[mt][nt][q] = 0.f;

    const float* Ap = A + (size_t)(bm + lr) * K + lc;
    const float* Bp = Bw + (size_t)(bn + lr) * K + lc;

    auto fill = [&](__nv_bfloat16* dh, __nv_bfloat16* dl,
                    float4 f0, float4 f1) {
        float v[8] = {f0.x, f0.y, f0.z, f0.w, f1.x, f1.y, f1.z, f1.w};
        unsigned hw[4], lw[4];
#pragma unroll
        for (int i = 0; i < 4; i++) {
            __nv_bfloat16 h0, l0, h1, l1;
            bf_split(v[2*i], h0, l0);
            bf_split(v[2*i+1], h1, l1);
            hw[i] = pack_bf2(h0, h1);
            lw[i] = pack_bf2(l0, l1);
        }
        *(uint4*)dh = make_uint4(hw[0], hw[1], hw[2], hw[3]);
        *(uint4*)dl = make_uint4(lw[0], lw[1], lw[2], lw[3]);
    };

    {
        float4 a0 = *(const float4*)(Ap);
        float4 a1 = *(const float4*)(Ap + 4);
        float4 b0 = *(const float4*)(Bp);
        float4 b1 = *(const float4*)(Bp + 4);
        fill(Ah + lr * 24 + lc, Al + lr * 24 + lc, a0, a1);
        fill(Bh + lr * 24 + lc, Bl + lr * 24 + lc, b0, b1);
    }
    __syncthreads();

    int cur = 0;
    for (int k0 = 0; k0 < K; k0 += 16) {
        bool more = (k0 + 16) < K;
        float4 ga0, ga1, gb0, gb1;
        if (more) {
            ga0 = *(const float4*)(Ap + k0 + 16);
            ga1 = *(const float4*)(Ap + k0 + 20);
            gb0 = *(const float4*)(Bp + k0 + 16);
            gb1 = *(const float4*)(Bp + k0 + 20);
        }
        const unsigned* ahw = (const unsigned*)(Ah + cur * 3072);
        const unsigned* alw = (const unsigned*)(Al + cur * 3072);
        const unsigned* bhw = (const unsigned*)(Bh + cur * 3072);
        const unsigned* blw = (const unsigned*)(Bl + cur * 3072);
        unsigned afh[2][4], afl[2][4];
#pragma unroll
        for (int mt = 0; mt < 2; mt++) {
            int m = wm + mt * 16 + gid;
            afh[mt][0] = ahw[m * 12 + tid4];
            afh[mt][1] = ahw[(m + 8) * 12 + tid4];
            afh[mt][2] = ahw[m * 12 + tid4 + 4];
            afh[mt][3] = ahw[(m + 8) * 12 + tid4 + 4];
            afl[mt][0] = alw[m * 12 + tid4];
            afl[mt][1] = alw[(m + 8) * 12 + tid4];
            afl[mt][2] = alw[m * 12 + tid4 + 4];
            afl[mt][3] = alw[(m + 8) * 12 + tid4 + 4];
        }
        unsigned bfh[8][2], bfl[8][2];
#pragma unroll
        for (int nt = 0; nt < 8; nt++) {
            int nn = wn + nt * 8 + gid;
            bfh[nt][0] = bhw[nn * 12 + tid4];
            bfh[nt][1] = bhw[nn * 12 + tid4 + 4];
            bfl[nt][0] = blw[nn * 12 + tid4];
            bfl[nt][1] = blw[nn * 12 + tid4 + 4];
        }
#pragma unroll
        for (int mt = 0; mt < 2; mt++)
#pragma unroll
            for (int nt = 0; nt < 8; nt++) {
                mma_bf16(c[mt][nt], afh[mt], bfh[nt][0], bfh[nt][1]);
                mma_bf16(c[mt][nt], afh[mt], bfl[nt][0], bfl[nt][1]);
                mma_bf16(c[mt][nt], afl[mt], bfh[nt][0], bfh[nt][1]);
            }
        if (more) {
            int nxt = cur ^ 1;
            fill(Ah + nxt * 3072 + lr * 24 + lc, Al + nxt * 3072 + lr * 24 + lc, ga0, ga1);
            fill(Bh + nxt * 3072 + lr * 24 + lc, Bl + nxt * 3072 + lr * 24 + lc, gb0, gb1);
            __syncthreads();
            cur = nxt;
        }
    }

#pragma unroll
    for (int mt = 0; mt < 2; mt++) {
        int row = bm + wm + mt * 16 + gid;
#pragma unroll
        for (int nt = 0; nt < 8; nt++) {
            int col = bn + wn + nt * 8 + tid4 * 2;
            float bv0 = bias1[col], bv1 = bias1[col + 1];
            if (bias2) { bv0 += bias2[col]; bv1 += bias2[col + 1]; }
            float r0 = c[mt][nt][0] + bv0;
            float r1 = c[mt][nt][1] + bv1;
            float r2 = c[mt][nt][2] + bv0;
            float r3 = c[mt][nt][3] + bv1;
            if (RELU) {
                r0 = fmaxf(r0, 0.f); r1 = fmaxf(r1, 0.f);
                r2 = fmaxf(r2, 0.f); r3 = fmaxf(r3, 0.f);
            }
            *(float2*)&C[(size_t)row * N + col]       = make_float2(r0, r1);
            *(float2*)&C[(size_t)(row + 8) * N + col] = make_float2(r2, r3);
        }
    }
}

// ======================================================================
// persistent LSTM: 128 CTAs, each owns 2 hidden units.  (proven)
// ======================================================================
#define NBLK 128
#define LSTM_SMEM ((2048 + 8224 + 64 + 576) * 4)
__device__ __forceinline__ float sigmoidf(float x) { return 1.f / (1.f + expf(-x)); }

__global__ void __launch_bounds__(256)
lstm_kernel(const float* __restrict__ done,
            const float* __restrict__ h0,
            const float* __restrict__ c0,
            const float* __restrict__ whh,
            float* __restrict__ out) {
    extern __shared__ float sm[];
    float* w_s = sm;             // [k=256][r=8]
    float* h_s = sm + 2048;      // [32][257]
    float* c_s = h_s + 8224;     // [64]
    float* p_s = c_s + 64;       // [2][32][9]
    int t = threadIdx.x, blk = blockIdx.x;
    int j0 = blk * 2;

    for (int i = t; i < 2048; i += 256) {
        int k = i >> 3, r = i & 7;
        int q = r >> 1, jj = r & 1;
        w_s[i] = whh[(size_t)(q * HID + j0 + jj) * HID + k];
    }
    if (t < 64) {
        int b = t >> 1, jj = t & 1;
        c_s[t] = c0[b * HID + j0 + jj];
    }
    __syncthreads();

    int u = t & 127, half = t >> 7;
    int gb = u & 31, rq = u >> 5;
    unsigned target = 0;

    for (int step = 0; step < TT; step++) {
        float2 acc0;
        if (half == 0)
            acc0 = *(const float2*)&g_gx[(size_t)(step * BB + gb) * 4 * HID + rq * HID + j0];
        else
            acc0 = make_float2(0.f, 0.f);
        u64t accp = pk2(acc0.x, acc0.y);

        const float* hsrc = (step == 0) ? h0 : g_h;
        for (int i = t; i < BB * HID; i += 256) {
            int b = i >> 8;
            h_s[b * 257 + (i & 255)] = hsrc[i] * (1.0f - __ldg(&done[step * BB + b]));
        }
        __syncthreads();

        {
            const float* hp = &h_s[gb * 257 + half * 128];
            const float* wp = &w_s[(half * 128) * 8 + rq * 2];
#pragma unroll 8
            for (int k = 0; k < 128; k++) {
                float hv = hp[k];
                u64t hh = pk2(hv, hv);
                u64t wv = *(const u64t*)&wp[k * 8];
                fma2(accp, hh, wv);
            }
            float2 r = upk2(accp);
            float* pp = &p_s[half * 288 + gb * 9 + rq * 2];
            pp[0] = r.x; pp[1] = r.y;
        }
        __syncthreads();

        if (t < 64) {
            int b = t >> 1, jj = t & 1;
            float m = 1.0f - __ldg(&done[step * BB + b]);
            const float* p0 = &p_s[b * 9];
            const float* p1 = &p_s[288 + b * 9];
            float gi = p0[0 + jj] + p1[0 + jj];
            float gf = p0[2 + jj] + p1[2 + jj];
            float gg = p0[4 + jj] + p1[4 + jj];
            float go = p0[6 + jj] + p1[6 + jj];
            float I = sigmoidf(gi);
            float F = sigmoidf(gf);
            float G = tanhf(gg);
            float O = sigmoidf(go);
            float c_new = F * (m * c_s[t]) + I * G;
            c_s[t] = c_new;
            float h_new = O * tanhf(c_new);
            g_h[b * HID + j0 + jj] = h_new;
            g_hs[(size_t)(step * BB + b) * HID + j0 + jj] = h_new;
            if (step == TT - 1) {
                out[OUT_H + b * HID + j0 + jj] = h_new;
                out[OUT_C + b * HID + j0 + jj] = c_new;
            }
        }
        __threadfence();
        __syncthreads();
        if (t == 0) {
            atomicAdd(&g_bar, 1u);
            target += NBLK;
            while (*(volatile unsigned*)&g_bar < target) { }
        }
        __syncthreads();
    }

    if (t == 0) {
        unsigned v = atomicAdd(&g_exit, 1u);
        if (v == NBLK - 1) {
            atomicExch(&g_exit, 0u);
            atomicExch(&g_bar, 0u);
            __threadfence();
        }
    }
}

// ======================================================================
// heads
// ======================================================================
__global__ void heads_kernel(const float* __restrict__ pw,
                             const float* __restrict__ pb,
                             const float* __restrict__ vw,
                             const float* __restrict__ vb,
                             float* __restrict__ out) {
    __shared__ float ws[7 * 256];
    int t = threadIdx.x;
    for (int i = t; i < 6 * 256; i += 256) ws[i] = pw[i];
    if (t < 256) ws[1536 + t] = vw[t];
    __syncthreads();

    int warp = t >> 5, lane = t & 31;
    int row = blockIdx.x * 8 + warp;
    const float* hrow = g_hs + (size_t)row * 256;
    float p[7];
#pragma unroll
    for (int a = 0; a < 7; a++) p[a] = 0.f;
    for (int k = lane; k < 256; k += 32) {
        float hv = hrow[k];
#pragma unroll
        for (int a = 0; a < 7; a++) p[a] += hv * ws[a * 256 + k];
    }
#pragma unroll
    for (int a = 0; a < 7; a++)
#pragma unroll
        for (int off = 16; off; off >>= 1)
            p[a] += __shfl_xor_sync(0xffffffffu, p[a], off);
    if (lane == 0) {
#pragma unroll
        for (int a = 0; a < 6; a++) out[(size_t)row * 6 + a] = p[a] + pb[a];
        out[OUT_V + row] = p[6] + vb[0];
    }
}

// ======================================================================
// launch
// ======================================================================
extern "C" void kernel_launch(void* const* d_in, const int* in_sizes, int n_in,
                              void* d_out, int out_size) {
    const float* image = (const float*)d_in[0];
    const float* done  = (const float*)d_in[1];
    const float* h0    = (const float*)d_in[2];
    const float* c0    = (const float*)d_in[3];
    const float* c1w   = (const float*)d_in[4];
    const float* c1b   = (const float*)d_in[5];
    const float* c2w   = (const float*)d_in[6];
    const float* c2b   = (const float*)d_in[7];
    const float* c3w   = (const float*)d_in[8];
    const float* c3b   = (const float*)d_in[9];
    const float* fcw   = (const float*)d_in[10];
    const float* fcb   = (const float*)d_in[11];
    const float* wih   = (const float*)d_in[12];
    const float* whh   = (const float*)d_in[13];
    const float* bih   = (const float*)d_in[14];
    const float* bhh   = (const float*)d_in[15];
    const float* polw  = (const float*)d_in[16];
    const float* polb  = (const float*)d_in[17];
    const float* valw  = (const float*)d_in[18];
    const float* valb  = (const float*)d_in[19];
    float* out = (float*)d_out;

    auto conv1 = conv_bf3_kernel<3, 8, 4, 84, 20, 32,  96, 4, 13, true>;
    auto conv2 = conv_bf3_kernel<32, 4, 2, 20, 9,  64, 128, 2, 6,  false>;

    cudaFuncSetAttribute(conv1, cudaFuncAttributeMaxDynamicSharedMemorySize, C1B_SMEM);
    cudaFuncSetAttribute(conv2, cudaFuncAttributeMaxDynamicSharedMemorySize, C2B_SMEM);
    cudaFuncSetAttribute(conv3_mma_kernel, cudaFuncAttributeMaxDynamicSharedMemorySize, C3M_SMEM);
    cudaFuncSetAttribute(gemm_bf3_kernel<true>,  cudaFuncAttributeMaxDynamicSharedMemorySize, GEMM_SMEM);
    cudaFuncSetAttribute(gemm_bf3_kernel<false>, cudaFuncAttributeMaxDynamicSharedMemorySize, GEMM_SMEM);
    cudaFuncSetAttribute(lstm_kernel, cudaFuncAttributeMaxDynamicSharedMemorySize, LSTM_SMEM);

    void *p_c1, *p_c2, *p_c3, *p_feat, *p_gx;
    cudaGetSymbolAddress(&p_c1, g_c1);
    cudaGetSymbolAddress(&p_c2, g_c2);
    cudaGetSymbolAddress(&p_c3, g_c3);
    cudaGetSymbolAddress(&p_feat, g_feat);
    cudaGetSymbolAddress(&p_gx, g_gx);

    conv1<<<NTB, 256, C1B_SMEM>>>(image, c1w, c1b, (float*)p_c1);
    conv2<<<NTB, 256, C2B_SMEM>>>((const float*)p_c1, c2w, c2b, (float*)p_c2);
    conv3_mma_kernel<<<NTB, 256, C3M_SMEM>>>((const float*)p_c2, c3w, c3b, (float*)p_c3);

    // feats = relu(flat @ fc_w^T + fc_b)   [4096,512]  (bf16x3 ~= fp32)
    gemm_bf3_kernel<true><<<dim3(FEAT / 128, NTB / 128), 256, GEMM_SMEM>>>(
        (const float*)p_c3, fcw, fcb, nullptr, (float*)p_feat, NTB, FEAT, FLAT);

    // gates_x = feats @ w_ih^T + b_ih + b_hh   [4096,1024]  (bf16x3 ~= fp32)
    gemm_bf3_kernel<false><<<dim3((4 * HID) / 128, NTB / 128), 256, GEMM_SMEM>>>(
        (const float*)p_feat, wih, bih, bhh, (float*)p_gx, NTB, 4 * HID, FEAT);

    lstm_kernel<<<NBLK, 256, LSTM_SMEM>>>(done, h0, c0, whh, out);

    heads_kernel<<<NTB / 8, 256>>>(polw, polb, valw, valb, out);
}

// round 12
// speedup vs baseline: 1.2019x; 1.0034x over previous
#include <cuda_runtime.h>
#include <cuda_bf16.h>
#include <math.h>

// ---------------- problem constants ----------------
#define TT   128
#define BB   32
#define NTB  4096            // T*B
#define HID  256
#define FEAT 512
#define FLAT 3136            // 64*7*7
#define NACT 6

// output layout: logits[4096*6], v[4096], h[32*256], c[32*256]
#define OUT_V    24576
#define OUT_H    28672
#define OUT_C    36864

// ---------------- packed f32x2 helpers (LSTM) ----------------
typedef unsigned long long u64t;
__device__ __forceinline__ u64t pk2(float lo, float hi) {
    u64t r;
    asm("mov.b64 %0, {%1, %2};" : "=l"(r) : "f"(lo), "f"(hi));
    return r;
}
__device__ __forceinline__ void fma2(u64t& d, u64t a, u64t b) {
    asm("fma.rn.f32x2 %0, %1, %2, %0;" : "+l"(d) : "l"(a), "l"(b));
}
__device__ __forceinline__ float2 upk2(u64t v) {
    float2 f;
    asm("mov.b64 {%0, %1}, %2;" : "=f"(f.x), "=f"(f.y) : "l"(v));
    return f;
}

// ---------------- bf16 helpers ----------------
__device__ __forceinline__ void mma_bf16(float c[4], const unsigned a[4],
                                         unsigned b0, unsigned b1) {
    asm volatile(
        "mma.sync.aligned.m16n8k16.row.col.f32.bf16.bf16.f32 "
        "{%0,%1,%2,%3}, {%4,%5,%6,%7}, {%8,%9}, {%0,%1,%2,%3};"
        : "+f"(c[0]), "+f"(c[1]), "+f"(c[2]), "+f"(c[3])
        : "r"(a[0]), "r"(a[1]), "r"(a[2]), "r"(a[3]), "r"(b0), "r"(b1));
}
__device__ __forceinline__ void bf_split(float x, __nv_bfloat16& h, __nv_bfloat16& l) {
    h = __float2bfloat16(x);
    l = __float2bfloat16(x - __bfloat162float(h));
}
__device__ __forceinline__ unsigned pack_bf2(__nv_bfloat16 a, __nv_bfloat16 b) {
    __nv_bfloat162 v(a, b);
    return *(unsigned*)&v;
}
__device__ __forceinline__ unsigned lo32(u64t v) { return (unsigned)v; }
__device__ __forceinline__ unsigned hi32(u64t v) { return (unsigned)(v >> 32); }

// ---------------- scratch ----------------
__device__ float g_c1[(size_t)NTB*32*20*20];
__device__ float g_c2[(size_t)NTB*64*9*9];
__device__ float g_c3[(size_t)NTB*64*7*7];
__device__ float g_feat[(size_t)NTB*FEAT];
__device__ float g_gx[(size_t)NTB*4*HID];
__device__ float g_hs[(size_t)NTB*HID];
__device__ float g_h[BB*HID];
__device__ unsigned g_bar;
__device__ unsigned g_exit;

// ======================================================================
// bf16x3 implicit-GEMM conv, hi/lo interleaved smem.
// MMA issue order: n-tile PAIRS, term-interleaved (hh j, hh j+1, hl j, ...)
// -> same-accumulator MMAs separated for ILP.  Numerics identical.
// ======================================================================
template<int CIN,int KW,int S,int IW,int OW,int MCH,int KC,int NG,int MAXNT,bool SCALE>
__global__ void __launch_bounds__(256, 2)
conv_bf3_kernel(const float* __restrict__ src,
                const float* __restrict__ w,
                const float* __restrict__ bias,
                float* __restrict__ dst) {
    constexpr int K    = CIN * KW * KW;
    constexpr int NPOS = OW * OW;
    constexpr int ISZ  = CIN * IW * IW;
    constexpr int NCH  = K / KC;
    constexpr int WSW  = KC + 2;
    constexpr int NTT  = (NPOS + 7) / 8;
    constexpr int IPAIR = ISZ / 2;

    extern __shared__ unsigned smw[];
    unsigned* iw = smw;                         // (IPAIR+8)*2 words
    unsigned* ww = iw + (IPAIR + 8) * 2;        // MCH*WSW words
    int* kof = (int*)(ww + MCH * WSW);          // [K]

    int n = blockIdx.x, t = threadIdx.x;

    const float* s = src + (size_t)n * ISZ;
    for (int i = t; i < IPAIR; i += 256) {
        float x0 = s[2 * i], x1 = s[2 * i + 1];
        if (SCALE) { x0 *= (1.0f / 255.0f); x1 *= (1.0f / 255.0f); }
        __nv_bfloat16 h0, l0, h1, l1;
        bf_split(x0, h0, l0);
        bf_split(x1, h1, l1);
        iw[2 * i]     = pack_bf2(h0, h1);
        iw[2 * i + 1] = pack_bf2(l0, l1);
    }
    if (t < 16) iw[IPAIR * 2 + t] = 0u;
    for (int i = t; i < K; i += 256) {
        int c = i / (KW * KW), r = i % (KW * KW);
        kof[i] = (c * IW + r / KW) * IW + (r % KW);
    }

    int wid = t >> 5, lane = t & 31;
    int gid = lane >> 2, tid4 = lane & 3;
    int wm, ng;
    if (MCH == 32) { wm = wid >> 2; ng = wid & 3; }
    else           { wm = wid >> 1; ng = wid & 1; }
    int m0 = wm * 16 + gid;

    int nbase[MAXNT];
    bool nval[MAXNT];
#pragma unroll
    for (int j = 0; j < MAXNT; j++) {
        int nt = ng + j * NG;
        int p = nt * 8 + gid;
        bool v = (nt < NTT) && (p < NPOS);
        nval[j] = v;
        int oy = p / OW, ox = p % OW;
        nbase[j] = v ? (oy * S * IW + ox * S) : 0;
    }

    float acc[MAXNT][4];
#pragma unroll
    for (int j = 0; j < MAXNT; j++)
        acc[j][0] = acc[j][1] = acc[j][2] = acc[j][3] = 0.f;

    for (int ck = 0; ck < NCH; ck++) {
        __syncthreads();
        for (int i = t; i < MCH * (KC / 2); i += 256) {
            int m = i / (KC / 2), q = i % (KC / 2);
            float x0 = w[(size_t)m * K + ck * KC + 2 * q];
            float x1 = w[(size_t)m * K + ck * KC + 2 * q + 1];
            __nv_bfloat16 h0, l0, h1, l1;
            bf_split(x0, h0, l0);
            bf_split(x1, h1, l1);
            ww[m * WSW + 2 * q]     = pack_bf2(h0, h1);
            ww[m * WSW + 2 * q + 1] = pack_bf2(l0, l1);
        }
        __syncthreads();

        for (int k16 = 0; k16 < KC / 16; k16++) {
            int wq = k16 * 8 + tid4;
            u64t A0 = *(const u64t*)&ww[m0 * WSW + 2 * wq];
            u64t A1 = *(const u64t*)&ww[(m0 + 8) * WSW + 2 * wq];
            u64t A2 = *(const u64t*)&ww[m0 * WSW + 2 * wq + 8];
            u64t A3 = *(const u64t*)&ww[(m0 + 8) * WSW + 2 * wq + 8];
            unsigned ah[4] = {lo32(A0), lo32(A1), lo32(A2), lo32(A3)};
            unsigned al[4] = {hi32(A0), hi32(A1), hi32(A2), hi32(A3)};

            int kbase = ck * KC + k16 * 16;
            int oa = kof[kbase + 2 * tid4];
            int ob = kof[kbase + 8 + 2 * tid4];
            // pairwise n-tiles, term-interleaved for accumulator ILP
#pragma unroll
            for (int j = 0; j < MAXNT; j += 2) {
                unsigned p0h, p1h, p0l, p1l;     // pair slot 0 (j)
                unsigned q0h, q1h, q0l, q1l;     // pair slot 1 (j+1)
                if (nval[j]) {
                    u64t B0 = *(const u64t*)&iw[(oa + nbase[j])];
                    u64t B1 = *(const u64t*)&iw[(ob + nbase[j])];
                    p0h = lo32(B0); p0l = hi32(B0);
                    p1h = lo32(B1); p1l = hi32(B1);
                } else { p0h = p1h = p0l = p1l = 0u; }
                if (j + 1 < MAXNT) {
                    if (nval[j + 1]) {
                        u64t B0 = *(const u64t*)&iw[(oa + nbase[j + 1])];
                        u64t B1 = *(const u64t*)&iw[(ob + nbase[j + 1])];
                        q0h = lo32(B0); q0l = hi32(B0);
                        q1h = lo32(B1); q1l = hi32(B1);
                    } else { q0h = q1h = q0l = q1l = 0u; }
                }
                mma_bf16(acc[j], ah, p0h, p1h);
                if (j + 1 < MAXNT) mma_bf16(acc[j + 1], ah, q0h, q1h);
                mma_bf16(acc[j], ah, p0l, p1l);
                if (j + 1 < MAXNT) mma_bf16(acc[j + 1], ah, q0l, q1l);
                mma_bf16(acc[j], al, p0h, p1h);
                if (j + 1 < MAXNT) mma_bf16(acc[j + 1], al, q0h, q1h);
            }
        }
    }

    float* base = dst + (size_t)n * MCH * NPOS;
    float b0 = __ldg(&bias[m0]);
    float b1 = __ldg(&bias[m0 + 8]);
#pragma unroll
    for (int j = 0; j < MAXNT; j++) {
        int nt = ng + j * NG;
        if (nt >= NTT) continue;
        int col = nt * 8 + tid4 * 2;
        if (col < NPOS) {
            base[(size_t)m0 * NPOS + col]       = fmaxf(acc[j][0] + b0, 0.f);
            base[(size_t)(m0 + 8) * NPOS + col] = fmaxf(acc[j][2] + b1, 0.f);
        }
        if (col + 1 < NPOS) {
            base[(size_t)m0 * NPOS + col + 1]       = fmaxf(acc[j][1] + b0, 0.f);
            base[(size_t)(m0 + 8) * NPOS + col + 1] = fmaxf(acc[j][3] + b1, 0.f);
        }
    }
}

#define C1B_SMEM (((21168/2 + 8) * 2 + 32 * 98) * 4 + 192 * 4)
#define C2B_SMEM (((12800/2 + 8) * 2 + 64 * 130) * 4 + 512 * 4)

// ======================================================================
// conv3 bf16x3 MMA (KW padded 3->4, dual shifted input planes),
// pairwise/term-interleaved MMA order.
// ======================================================================
#define C3M_ISZ   5184
#define C3M_IPAIR 2592
#define C3M_IWRDS ((C3M_IPAIR + 8) * 2)
#define C3M_WSW   194
#define C3M_SMEM  ((2 * C3M_IWRDS + 64 * C3M_WSW) * 4 + 768 * 4)
__global__ void __launch_bounds__(256, 2)
conv3_mma_kernel(const float* __restrict__ src,
                 const float* __restrict__ w,
                 const float* __restrict__ bias,
                 float* __restrict__ dst) {
    constexpr int IW = 9, OW = 7, NPOS = 49, MCH = 64;
    constexpr int K = 768, KC = 192, NCH = 4;
    constexpr int NTT = 7, NG = 2, MAXNT = 4;

    extern __shared__ unsigned smw[];
    unsigned* iw = smw;
    unsigned* jw = iw + C3M_IWRDS;
    unsigned* ww = jw + C3M_IWRDS;
    int* kof = (int*)(ww + 64 * C3M_WSW);

    int n = blockIdx.x, t = threadIdx.x;
    const float* s = src + (size_t)n * C3M_ISZ;

    for (int u = t; u < C3M_IPAIR + 8; u += 256) {
        float x0 = (2*u   < C3M_ISZ) ? s[2*u]   : 0.f;
        float x1 = (2*u+1 < C3M_ISZ) ? s[2*u+1] : 0.f;
        float x2 = (2*u+2 < C3M_ISZ) ? s[2*u+2] : 0.f;
        __nv_bfloat16 h0,l0,h1,l1,h2,l2;
        bf_split(x0,h0,l0); bf_split(x1,h1,l1); bf_split(x2,h2,l2);
        iw[2*u]   = pack_bf2(h0,h1); iw[2*u+1] = pack_bf2(l0,l1);
        jw[2*u]   = pack_bf2(h1,h2); jw[2*u+1] = pack_bf2(l1,l2);
    }
    for (int i = t; i < K; i += 256) {
        int kx = i & 3, ky = (i >> 2) % 3, c = i / 12;
        kof[i] = c * 81 + ky * 9 + kx;
    }

    int wid = t >> 5, lane = t & 31;
    int gid = lane >> 2, tid4 = lane & 3;
    int wm = wid >> 1, ng = wid & 1;
    int m0 = wm * 16 + gid;

    int nbase[MAXNT];
    bool nval[MAXNT];
#pragma unroll
    for (int j = 0; j < MAXNT; j++) {
        int nt = ng + j * NG;
        int p = nt * 8 + gid;
        bool v = (nt < NTT) && (p < NPOS);
        nval[j] = v;
        int oy = p / OW, ox = p % OW;
        nbase[j] = v ? (oy * IW + ox) : 0;
    }

    float acc[MAXNT][4];
#pragma unroll
    for (int j = 0; j < MAXNT; j++)
        acc[j][0] = acc[j][1] = acc[j][2] = acc[j][3] = 0.f;

    for (int ck = 0; ck < NCH; ck++) {
        __syncthreads();
        for (int i = t; i < MCH * (KC / 2); i += 256) {
            int m = i / (KC / 2), q = i % (KC / 2);
            int k = ck * KC + 2 * q;
            int kx = k & 3, ky = (k >> 2) % 3, c = k / 12;
            float x0 = w[((size_t)(m * 64 + c) * 3 + ky) * 3 + kx];
            float x1 = (kx == 0) ? w[((size_t)(m * 64 + c) * 3 + ky) * 3 + 1] : 0.f;
            __nv_bfloat16 h0, l0, h1, l1;
            bf_split(x0, h0, l0);
            bf_split(x1, h1, l1);
            ww[m * C3M_WSW + 2 * q]     = pack_bf2(h0, h1);
            ww[m * C3M_WSW + 2 * q + 1] = pack_bf2(l0, l1);
        }
        __syncthreads();

        for (int k16 = 0; k16 < KC / 16; k16++) {
            int wq = k16 * 8 + tid4;
            u64t A0 = *(const u64t*)&ww[m0 * C3M_WSW + 2 * wq];
            u64t A1 = *(const u64t*)&ww[(m0 + 8) * C3M_WSW + 2 * wq];
            u64t A2 = *(const u64t*)&ww[m0 * C3M_WSW + 2 * wq + 8];
            u64t A3 = *(const u64t*)&ww[(m0 + 8) * C3M_WSW + 2 * wq + 8];
            unsigned ah[4] = {lo32(A0), lo32(A1), lo32(A2), lo32(A3)};
            unsigned al[4] = {hi32(A0), hi32(A1), hi32(A2), hi32(A3)};

            int kbase = ck * KC + k16 * 16;
            int oa = kof[kbase + 2 * tid4];
            int ob = kof[kbase + 8 + 2 * tid4];
#pragma unroll
            for (int j = 0; j < MAXNT; j += 2) {
                unsigned p0h, p1h, p0l, p1l, q0h, q1h, q0l, q1l;
                if (nval[j]) {
                    int e0 = oa + nbase[j];
                    int e1 = ob + nbase[j];
                    const unsigned* pp0 = (e0 & 1) ? (jw + e0 - 1) : (iw + e0);
                    const unsigned* pp1 = (e1 & 1) ? (jw + e1 - 1) : (iw + e1);
                    u64t B0 = *(const u64t*)pp0;
                    u64t B1 = *(const u64t*)pp1;
                    p0h = lo32(B0); p0l = hi32(B0);
                    p1h = lo32(B1); p1l = hi32(B1);
                } else { p0h = p1h = p0l = p1l = 0u; }
                if (nval[j + 1]) {
                    int e0 = oa + nbase[j + 1];
                    int e1 = ob + nbase[j + 1];
                    const unsigned* pp0 = (e0 & 1) ? (jw + e0 - 1) : (iw + e0);
                    const unsigned* pp1 = (e1 & 1) ? (jw + e1 - 1) : (iw + e1);
                    u64t B0 = *(const u64t*)pp0;
                    u64t B1 = *(const u64t*)pp1;
                    q0h = lo32(B0); q0l = hi32(B0);
                    q1h = lo32(B1); q1l = hi32(B1);
                } else { q0h = q1h = q0l = q1l = 0u; }
                mma_bf16(acc[j],     ah, p0h, p1h);
                mma_bf16(acc[j + 1], ah, q0h, q1h);
                mma_bf16(acc[j],     ah, p0l, p1l);
                mma_bf16(acc[j + 1], ah, q0l, q1l);
                mma_bf16(acc[j],     al, p0h, p1h);
                mma_bf16(acc[j + 1], al, q0h, q1h);
            }
        }
    }

    float* base = dst + (size_t)n * MCH * NPOS;
    float b0 = __ldg(&bias[m0]);
    float b1 = __ldg(&bias[m0 + 8]);
#pragma unroll
    for (int j = 0; j < MAXNT; j++) {
        int nt = ng + j * NG;
        if (nt >= NTT) continue;
        int col = nt * 8 + tid4 * 2;
        if (col < NPOS) {
            base[(size_t)m0 * NPOS + col]       = fmaxf(acc[j][0] + b0, 0.f);
            base[(size_t)(m0 + 8) * NPOS + col] = fmaxf(acc[j][2] + b1, 0.f);
        }
        if (col + 1 < NPOS) {
            base[(size_t)m0 * NPOS + col + 1]       = fmaxf(acc[j][1] + b0, 0.f);
            base[(size_t)(m0 + 8) * NPOS + col + 1] = fmaxf(acc[j][3] + b1, 0.f);
        }
    }
}

// ======================================================================
// bf16x3 GEMM (round-9 base), TERM-MAJOR MMA order for accumulator ILP.
// ======================================================================
#define GEMM_SMEM 49152
template <bool RELU>
__global__ void __launch_bounds__(256)
gemm_bf3_kernel(const float* __restrict__ A,
                const float* __restrict__ Bw,
                const float* __restrict__ bias1,
                const float* __restrict__ bias2,
                float* __restrict__ C,
                int M, int N, int K) {
    extern __shared__ __nv_bfloat16 gsm[];
    __nv_bfloat16* Ah = gsm;            // [2][128][24]
    __nv_bfloat16* Al = gsm + 6144;
    __nv_bfloat16* Bh = gsm + 12288;
    __nv_bfloat16* Bl = gsm + 18432;

    int bm = blockIdx.y * 128, bn = blockIdx.x * 128;
    int t = threadIdx.x;
    int wid = t >> 5, lane = t & 31;
    int gid = lane >> 2, tid4 = lane & 3;
    int wm = (wid >> 1) * 32;
    int wn = (wid & 1) * 64;
    int lr = t >> 1, lc = (t & 1) * 8;

    float c[2][8][4];
#pragma unroll
    for (int mt = 0; mt < 2; mt++)
#pragma unroll
        for (int nt = 0; nt < 8; nt++)
#pragma unroll
            for (int q = 0; q < 4; q++) c[mt][nt][q] = 0.f;

    const float* Ap = A + (size_t)(bm + lr) * K + lc;
    const float* Bp = Bw + (size_t)(bn + lr) * K + lc;

    auto fill = [&](__nv_bfloat16* dh, __nv_bfloat16* dl,
                    float4 f0, float4 f1) {
        float v[8] = {f0.x, f0.y, f0.z, f0.w, f1.x, f1.y, f1.z, f1.w};
        unsigned hw[4], lw[4];
#pragma unroll
        for (int i = 0; i < 4; i++) {
            __nv_bfloat16 h0, l0, h1, l1;
            bf_split(v[2*i], h0, l0);
            bf_split(v[2*i+1], h1, l1);
            hw[i] = pack_bf2(h0, h1);
            lw[i] = pack_bf2(l0, l1);
        }
        *(uint4*)dh = make_uint4(hw[0], hw[1], hw[2], hw[3]);
        *(uint4*)dl = make_uint4(lw[0], lw[1], lw[2], lw[3]);
    };

    {
        float4 a0 = *(const float4*)(Ap);
        float4 a1 = *(const float4*)(Ap + 4);
        float4 b0 = *(const float4*)(Bp);
        float4 b1 = *(const float4*)(Bp + 4);
        fill(Ah + lr * 24 + lc, Al + lr * 24 + lc, a0, a1);
        fill(Bh + lr * 24 + lc, Bl + lr * 24 + lc, b0, b1);
    }
    __syncthreads();

    int cur = 0;
    for (int k0 = 0; k0 < K; k0 += 16) {
        bool more = (k0 + 16) < K;
        float4 ga0, ga1, gb0, gb1;
        if (more) {
            ga0 = *(const float4*)(Ap + k0 + 16);
            ga1 = *(const float4*)(Ap + k0 + 20);
            gb0 = *(const float4*)(Bp + k0 + 16);
            gb1 = *(const float4*)(Bp + k0 + 20);
        }
        const unsigned* ahw = (const unsigned*)(Ah + cur * 3072);
        const unsigned* alw = (const unsigned*)(Al + cur * 3072);
        const unsigned* bhw = (const unsigned*)(Bh + cur * 3072);
        const unsigned* blw = (const unsigned*)(Bl + cur * 3072);
        unsigned afh[2][4], afl[2][4];
#pragma unroll
        for (int mt = 0; mt < 2; mt++) {
            int m = wm + mt * 16 + gid;
            afh[mt][0] = ahw[m * 12 + tid4];
            afh[mt][1] = ahw[(m + 8) * 12 + tid4];
            afh[mt][2] = ahw[m * 12 + tid4 + 4];
            afh[mt][3] = ahw[(m + 8) * 12 + tid4 + 4];
            afl[mt][0] = alw[m * 12 + tid4];
            afl[mt][1] = alw[(m + 8) * 12 + tid4];
            afl[mt][2] = alw[m * 12 + tid4 + 4];
            afl[mt][3] = alw[(m + 8) * 12 + tid4 + 4];
        }
        unsigned bfh[8][2], bfl[8][2];
#pragma unroll
        for (int nt = 0; nt < 8; nt++) {
            int nn = wn + nt * 8 + gid;
            bfh[nt][0] = bhw[nn * 12 + tid4];
            bfh[nt][1] = bhw[nn * 12 + tid4 + 4];
            bfl[nt][0] = blw[nn * 12 + tid4];
            bfl[nt][1] = blw[nn * 12 + tid4 + 4];
        }
        // term-major: 16 independent MMAs between same-accumulator reuse
#pragma unroll
        for (int mt = 0; mt < 2; mt++)
#pragma unroll
            for (int nt = 0; nt < 8; nt++)
                mma_bf16(c[mt][nt], afh[mt], bfh[nt][0], bfh[nt][1]);
#pragma unroll
        for (int mt = 0; mt < 2; mt++)
#pragma unroll
            for (int nt = 0; nt < 8; nt++)
                mma_bf16(c[mt][nt], afh[mt], bfl[nt][0], bfl[nt][1]);
#pragma unroll
        for (int mt = 0; mt < 2; mt++)
#pragma unroll
            for (int nt = 0; nt < 8; nt++)
                mma_bf16(c[mt][nt], afl[mt], bfh[nt][0], bfh[nt][1]);
        if (more) {
            int nxt = cur ^ 1;
            fill(Ah + nxt * 3072 + lr * 24 + lc, Al + nxt * 3072 + lr * 24 + lc, ga0, ga1);
            fill(Bh + nxt * 3072 + lr * 24 + lc, Bl + nxt * 3072 + lr * 24 + lc, gb0, gb1);
            __syncthreads();
            cur = nxt;
        }
    }

#pragma unroll
    for (int mt = 0; mt < 2; mt++) {
        int row = bm + wm + mt * 16 + gid;
#pragma unroll
        for (int nt = 0; nt < 8; nt++) {
            int col = bn + wn + nt * 8 + tid4 * 2;
            float bv0 = bias1[col], bv1 = bias1[col + 1];
            if (bias2) { bv0 += bias2[col]; bv1 += bias2[col + 1]; }
            float r0 = c[mt][nt][0] + bv0;
            float r1 = c[mt][nt][1] + bv1;
            float r2 = c[mt][nt][2] + bv0;
            float r3 = c[mt][nt][3] + bv1;
            if (RELU) {
                r0 = fmaxf(r0, 0.f); r1 = fmaxf(r1, 0.f);
                r2 = fmaxf(r2, 0.f); r3 = fmaxf(r3, 0.f);
            }
            *(float2*)&C[(size_t)row * N + col]       = make_float2(r0, r1);
            *(float2*)&C[(size_t)(row + 8) * N + col] = make_float2(r2, r3);
        }
    }
}

// ======================================================================
// persistent LSTM: 128 CTAs, each owns 2 hidden units.  (proven)
// ======================================================================
#define NBLK 128
#define LSTM_SMEM ((2048 + 8224 + 64 + 576) * 4)
__device__ __forceinline__ float sigmoidf(float x) { return 1.f / (1.f + expf(-x)); }

__global__ void __launch_bounds__(256)
lstm_kernel(const float* __restrict__ done,
            const float* __restrict__ h0,
            const float* __restrict__ c0,
            const float* __restrict__ whh,
            float* __restrict__ out) {
    extern __shared__ float sm[];
    float* w_s = sm;             // [k=256][r=8]
    float* h_s = sm + 2048;      // [32][257]
    float* c_s = h_s + 8224;     // [64]
    float* p_s = c_s + 64;       // [2][32][9]
    int t = threadIdx.x, blk = blockIdx.x;
    int j0 = blk * 2;

    for (int i = t; i < 2048; i += 256) {
        int k = i >> 3, r = i & 7;
        int q = r >> 1, jj = r & 1;
        w_s[i] = whh[(size_t)(q * HID + j0 + jj) * HID + k];
    }
    if (t < 64) {
        int b = t >> 1, jj = t & 1;
        c_s[t] = c0[b * HID + j0 + jj];
    }
    __syncthreads();

    int u = t & 127, half = t >> 7;
    int gb = u & 31, rq = u >> 5;
    unsigned target = 0;

    for (int step = 0; step < TT; step++) {
        float2 acc0;
        if (half == 0)
            acc0 = *(const float2*)&g_gx[(size_t)(step * BB + gb) * 4 * HID + rq * HID + j0];
        else
            acc0 = make_float2(0.f, 0.f);
        u64t accp = pk2(acc0.x, acc0.y);

        const float* hsrc = (step == 0) ? h0 : g_h;
        for (int i = t; i < BB * HID; i += 256) {
            int b = i >> 8;
            h_s[b * 257 + (i & 255)] = hsrc[i] * (1.0f - __ldg(&done[step * BB + b]));
        }
        __syncthreads();

        {
            const float* hp = &h_s[gb * 257 + half * 128];
            const float* wp = &w_s[(half * 128) * 8 + rq * 2];
#pragma unroll 8
            for (int k = 0; k < 128; k++) {
                float hv = hp[k];
                u64t hh = pk2(hv, hv);
                u64t wv = *(const u64t*)&wp[k * 8];
                fma2(accp, hh, wv);
            }
            float2 r = upk2(accp);
            float* pp = &p_s[half * 288 + gb * 9 + rq * 2];
            pp[0] = r.x; pp[1] = r.y;
        }
        __syncthreads();

        if (t < 64) {
            int b = t >> 1, jj = t & 1;
            float m = 1.0f - __ldg(&done[step * BB + b]);
            const float* p0 = &p_s[b * 9];
            const float* p1 = &p_s[288 + b * 9];
            float gi = p0[0 + jj] + p1[0 + jj];
            float gf = p0[2 + jj] + p1[2 + jj];
            float gg = p0[4 + jj] + p1[4 + jj];
            float go = p0[6 + jj] + p1[6 + jj];
            float I = sigmoidf(gi);
            float F = sigmoidf(gf);
            float G = tanhf(gg);
            float O = sigmoidf(go);
            float c_new = F * (m * c_s[t]) + I * G;
            c_s[t] = c_new;
            float h_new = O * tanhf(c_new);
            g_h[b * HID + j0 + jj] = h_new;
            g_hs[(size_t)(step * BB + b) * HID + j0 + jj] = h_new;
            if (step == TT - 1) {
                out[OUT_H + b * HID + j0 + jj] = h_new;
                out[OUT_C + b * HID + j0 + jj] = c_new;
            }
        }
        __threadfence();
        __syncthreads();
        if (t == 0) {
            atomicAdd(&g_bar, 1u);
            target += NBLK;
            while (*(volatile unsigned*)&g_bar < target) { }
        }
        __syncthreads();
    }

    if (t == 0) {
        unsigned v = atomicAdd(&g_exit, 1u);
        if (v == NBLK - 1) {
            atomicExch(&g_exit, 0u);
            atomicExch(&g_bar, 0u);
            __threadfence();
        }
    }
}

// ======================================================================
// heads
// ======================================================================
__global__ void heads_kernel(const float* __restrict__ pw,
                             const float* __restrict__ pb,
                             const float* __restrict__ vw,
                             const float* __restrict__ vb,
                             float* __restrict__ out) {
    __shared__ float ws[7 * 256];
    int t = threadIdx.x;
    for (int i = t; i < 6 * 256; i += 256) ws[i] = pw[i];
    if (t < 256) ws[1536 + t] = vw[t];
    __syncthreads();

    int warp = t >> 5, lane = t & 31;
    int row = blockIdx.x * 8 + warp;
    const float* hrow = g_hs + (size_t)row * 256;
    float p[7];
#pragma unroll
    for (int a = 0; a < 7; a++) p[a] = 0.f;
    for (int k = lane; k < 256; k += 32) {
        float hv = hrow[k];
#pragma unroll
        for (int a = 0; a < 7; a++) p[a] += hv * ws[a * 256 + k];
    }
#pragma unroll
    for (int a = 0; a < 7; a++)
#pragma unroll
        for (int off = 16; off; off >>= 1)
            p[a] += __shfl_xor_sync(0xffffffffu, p[a], off);
    if (lane == 0) {
#pragma unroll
        for (int a = 0; a < 6; a++) out[(size_t)row * 6 + a] = p[a] + pb[a];
        out[OUT_V + row] = p[6] + vb[0];
    }
}

// ======================================================================
// launch
// ======================================================================
extern "C" void kernel_launch(void* const* d_in, const int* in_sizes, int n_in,
                              void* d_out, int out_size) {
    const float* image = (const float*)d_in[0];
    const float* done  = (const float*)d_in[1];
    const float* h0    = (const float*)d_in[2];
    const float* c0    = (const float*)d_in[3];
    const float* c1w   = (const float*)d_in[4];
    const float* c1b   = (const float*)d_in[5];
    const float* c2w   = (const float*)d_in[6];
    const float* c2b   = (const float*)d_in[7];
    const float* c3w   = (const float*)d_in[8];
    const float* c3b   = (const float*)d_in[9];
    const float* fcw   = (const float*)d_in[10];
    const float* fcb   = (const float*)d_in[11];
    const float* wih   = (const float*)d_in[12];
    const float* whh   = (const float*)d_in[13];
    const float* bih   = (const float*)d_in[14];
    const float* bhh   = (const float*)d_in[15];
    const float* polw  = (const float*)d_in[16];
    const float* polb  = (const float*)d_in[17];
    const float* valw  = (const float*)d_in[18];
    const float* valb  = (const float*)d_in[19];
    float* out = (float*)d_out;

    auto conv1 = conv_bf3_kernel<3, 8, 4, 84, 20, 32,  96, 4, 13, true>;
    auto conv2 = conv_bf3_kernel<32, 4, 2, 20, 9,  64, 128, 2, 6,  false>;

    cudaFuncSetAttribute(conv1, cudaFuncAttributeMaxDynamicSharedMemorySize, C1B_SMEM);
    cudaFuncSetAttribute(conv2, cudaFuncAttributeMaxDynamicSharedMemorySize, C2B_SMEM);
    cudaFuncSetAttribute(conv3_mma_kernel, cudaFuncAttributeMaxDynamicSharedMemorySize, C3M_SMEM);
    cudaFuncSetAttribute(gemm_bf3_kernel<true>,  cudaFuncAttributeMaxDynamicSharedMemorySize, GEMM_SMEM);
    cudaFuncSetAttribute(gemm_bf3_kernel<false>, cudaFuncAttributeMaxDynamicSharedMemorySize, GEMM_SMEM);
    cudaFuncSetAttribute(lstm_kernel, cudaFuncAttributeMaxDynamicSharedMemorySize, LSTM_SMEM);

    void *p_c1, *p_c2, *p_c3, *p_feat, *p_gx;
    cudaGetSymbolAddress(&p_c1, g_c1);
    cudaGetSymbolAddress(&p_c2, g_c2);
    cudaGetSymbolAddress(&p_c3, g_c3);
    cudaGetSymbolAddress(&p_feat, g_feat);
    cudaGetSymbolAddress(&p_gx, g_gx);

    conv1<<<NTB, 256, C1B_SMEM>>>(image, c1w, c1b, (float*)p_c1);
    conv2<<<NTB, 256, C2B_SMEM>>>((const float*)p_c1, c2w, c2b, (float*)p_c2);
    conv3_mma_kernel<<<NTB, 256, C3M_SMEM>>>((const float*)p_c2, c3w, c3b, (float*)p_c3);

    // feats = relu(flat @ fc_w^T + fc_b)   [4096,512]  (bf16x3 ~= fp32)
    gemm_bf3_kernel<true><<<dim3(FEAT / 128, NTB / 128), 256, GEMM_SMEM>>>(
        (const float*)p_c3, fcw, fcb, nullptr, (float*)p_feat, NTB, FEAT, FLAT);

    // gates_x = feats @ w_ih^T + b_ih + b_hh   [4096,1024]  (bf16x3 ~= fp32)
    gemm_bf3_kernel<false><<<dim3((4 * HID) / 128, NTB / 128), 256, GEMM_SMEM>>>(
        (const float*)p_feat, wih, bih, bhh, (float*)p_gx, NTB, 4 * HID, FEAT);

    lstm_kernel<<<NBLK, 256, LSTM_SMEM>>>(done, h0, c0, whh, out);

    heads_kernel<<<NTB / 8, 256>>>(polw, polb, valw, valb, out);
}